// round 5
// baseline (speedup 1.0000x reference)
#include <cuda_runtime.h>

// Problem constants
#define N_PTS   16384
#define M_REF   4096
#define L_LAYERS 8
#define KMAX    7                    // Fourier order; trunc err ~ 2*sum_{k>7} I_k(2) ~ 6e-5
#define RNK     (2*KMAX + 1)         // 15 features per coordinate
#define RPAD    16                   // padded row length (float4-aligned)
#define R2      (RNK*RNK)            // 225
#define SPAD    (RNK*RPAD)           // 240
#define SBLK    32                   // blocks computing S partials
#define MPB     128                  // reference points per S-block
#define TPB     128
#define SCALE   4.4711032452e-6f     // exp(-4) / 4096

// Scratch (device globals; no allocation allowed)
__device__ float2 g_feats[N_PTS];
__device__ float  g_SpartT[R2 * SBLK];   // transposed: [e][p] for coalesced reduce

// c_0 = I_0(2), c_k = 2*I_k(2)
__constant__ float C_BES[KMAX + 1] = {
    2.27958530f, 3.18127371f, 1.37789690f, 0.42547992f,
    0.10145715f, 0.01965093f, 3.2003260e-3f, 4.4927600e-4f
};

__device__ __forceinline__ float ex2_approx(float d) {
    float r; asm("ex2.approx.ftz.f32 %0, %1;" : "=f"(r) : "f"(d)); return r;
}
__device__ __forceinline__ float rcp_approx(float d) {
    float r; asm("rcp.approx.ftz.f32 %0, %1;" : "=f"(r) : "f"(d)); return r;
}
// tanh via e^{2x}: 1 - 2/(e^{2x}+1). Saturates correctly. Rel err ~1e-6.
__device__ __forceinline__ float fast_tanh(float x) {
    float e = ex2_approx(x * 2.8853900817779268f);
    return fmaf(-2.0f, rcp_approx(e + 1.0f), 1.0f);
}

// Fourier features via MUFU sin/cos + Chebyshev recurrence.
// out[0] = w0; out[k] = w_k cos(k a); out[KMAX+k] = w_k sin(k a), k=1..KMAX.
// WEIGHTED: w_k = C_BES[k] * wscale;  else w_k = 1.
template <bool WEIGHTED>
__device__ __forceinline__ void four_feats(float ang, float* out, float wscale) {
    float s = __sinf(ang);
    float c = __cosf(ang);
    float c2 = 2.0f * c;
    float ckm = 1.0f, skm = 0.0f;
    float ck  = c,    sk  = s;
    out[0] = WEIGHTED ? C_BES[0] * wscale : 1.0f;
    #pragma unroll
    for (int k = 1; k <= KMAX; k++) {
        float w = WEIGHTED ? C_BES[k] * wscale : 1.0f;
        out[k]        = w * ck;
        out[KMAX + k] = w * sk;
        float cn = fmaf(c2, ck, -ckm);
        float sn = fmaf(c2, sk, -skm);
        ckm = ck; skm = sk; ck = cn; sk = sn;
    }
}

// -------------------------------------------------------------------------
// Kernel 1: blocks [0,32):  partial S matrices (128 ref points each),
//                           written transposed g_SpartT[e*SBLK + b].
//           blocks [32,160): 8-layer tanh chain (128 data points each).
// -------------------------------------------------------------------------
__global__ void __launch_bounds__(TPB) prep_kernel(
    const float* __restrict__ x,
    const float* __restrict__ layer_W,
    const float* __restrict__ layer_b,
    const float* __restrict__ layer_scale,
    const float* __restrict__ layer_shift,
    const float* __restrict__ refset)
{
    __shared__ float V0[MPB][RNK];
    __shared__ float V1[MPB][RNK];

    int b = blockIdx.x;
    if (b < SBLK) {
        int m = b * MPB + threadIdx.x;
        float g0 = refset[2 * m + 0];
        float g1 = refset[2 * m + 1];
        float v0[RNK], v1[RNK];
        four_feats<true>(g0, v0, SCALE);   // e^-4/M folded into v0 weights
        four_feats<true>(g1, v1, 1.0f);
        #pragma unroll
        for (int i = 0; i < RNK; i++) {
            V0[threadIdx.x][i] = v0[i];
            V1[threadIdx.x][i] = v1[i];
        }
        __syncthreads();

        int e0 = threadIdx.x;            // < 128, always valid (R2=225)
        int e1 = threadIdx.x + TPB;      // valid if < 225
        int j0 = e0 / RNK, k0 = e0 - j0 * RNK;
        int j1 = e1 / RNK, k1 = e1 - j1 * RNK;
        bool has1 = (e1 < R2);

        float a0 = 0.f, a1 = 0.f, b0 = 0.f, b1 = 0.f;
        #pragma unroll 4
        for (int mm = 0; mm < MPB; mm += 2) {
            a0 = fmaf(V0[mm + 0][j0], V1[mm + 0][k0], a0);
            a1 = fmaf(V0[mm + 1][j0], V1[mm + 1][k0], a1);
            if (has1) {
                b0 = fmaf(V0[mm + 0][j1], V1[mm + 0][k1], b0);
                b1 = fmaf(V0[mm + 1][j1], V1[mm + 1][k1], b1);
            }
        }
        g_SpartT[e0 * SBLK + b] = a0 + a1;
        if (has1) g_SpartT[e1 * SBLK + b] = b0 + b1;
    } else {
        int n = (b - SBLK) * TPB + threadIdx.x;
        float h0 = x[2 * n + 0];
        float h1 = x[2 * n + 1];
        #pragma unroll
        for (int l = 0; l < L_LAYERS; l++) {
            float w00 = layer_W[l * 4 + 0], w01 = layer_W[l * 4 + 1];
            float w10 = layer_W[l * 4 + 2], w11 = layer_W[l * 4 + 3];
            float c0  = layer_b[l * 2 + 0],  c1  = layer_b[l * 2 + 1];
            float sc0 = layer_scale[l * 2 + 0], sc1 = layer_scale[l * 2 + 1];
            float t0  = layer_shift[l * 2 + 0], t1  = layer_shift[l * 2 + 1];
            float u0 = fast_tanh(fmaf(h0, w00, fmaf(h1, w01, c0)));
            float u1 = fast_tanh(fmaf(h0, w10, fmaf(h1, w11, c1)));
            h0 = fmaf(u0, sc0, t0);
            h1 = fmaf(u1, sc1, t1);
        }
        g_feats[n] = make_float2(h0, h1);
    }
}

// -------------------------------------------------------------------------
// Kernel 2: per-block stateless S reduction (16 LDG.128/thread, L2-resident),
//           per-n bilinear form + MLP + softmax.
// -------------------------------------------------------------------------
__global__ void __launch_bounds__(TPB) final_kernel(
    const float* __restrict__ W1,
    const float* __restrict__ b1,
    const float* __restrict__ W2,
    const float* __restrict__ b2,
    float* __restrict__ out)
{
    __shared__ __align__(16) float S[SPAD];   // 15 rows x 16 (pad col = 0)

    int n = blockIdx.x * TPB + threadIdx.x;
    float2 f = g_feats[n];                    // issue early

    // Reduce 32 transposed partials: each thread covers elements tid, tid+128.
    #pragma unroll
    for (int pass = 0; pass < 2; pass++) {
        int e = threadIdx.x + pass * TPB;
        if (e < R2) {
            const float4* src = (const float4*)(g_SpartT + e * SBLK);
            float4 s0 = src[0], s1 = src[1], s2 = src[2], s3 = src[3];
            float4 s4 = src[4], s5 = src[5], s6 = src[6], s7 = src[7];
            float r = (((s0.x + s0.y) + (s0.z + s0.w)) + ((s1.x + s1.y) + (s1.z + s1.w)))
                    + (((s2.x + s2.y) + (s2.z + s2.w)) + ((s3.x + s3.y) + (s3.z + s3.w)))
                    + (((s4.x + s4.y) + (s4.z + s4.w)) + ((s5.x + s5.y) + (s5.z + s5.w)))
                    + (((s6.x + s6.y) + (s6.z + s6.w)) + ((s7.x + s7.y) + (s7.z + s7.w)));
            int j = e / RNK, k = e - j * RNK;
            S[j * RPAD + k] = r;
        } else if (e < SPAD) {
            int j = e - R2;                   // pad column
            S[j * RPAD + (RPAD - 1)] = 0.0f;
        }
    }

    // Trig features (overlaps S-load latency before the sync)
    float u0[RNK];
    __align__(16) float u1[RPAD];
    four_feats<false>(f.x, u0, 1.0f);
    four_feats<false>(f.y, u1, 1.0f);
    u1[RPAD - 1] = 0.0f;

    __syncthreads();

    const float4* u1v = (const float4*)u1;
    float agg = 0.0f;
    #pragma unroll
    for (int j = 0; j < RNK; j++) {
        const float4* Sv = (const float4*)(S + j * RPAD);
        float t0 = 0.f, t1 = 0.f, t2 = 0.f, t3 = 0.f;
        #pragma unroll
        for (int q = 0; q < RPAD / 4; q++) {
            float4 sv = Sv[q];
            float4 uv = u1v[q];
            t0 = fmaf(sv.x, uv.x, t0);
            t1 = fmaf(sv.y, uv.y, t1);
            t2 = fmaf(sv.z, uv.z, t2);
            t3 = fmaf(sv.w, uv.w, t3);
        }
        agg = fmaf(u0[j], (t0 + t1) + (t2 + t3), agg);
    }

    // tiny MLP + 2-way softmax (fast approx)
    float h[4];
    #pragma unroll
    for (int j = 0; j < 4; j++)
        h[j] = fast_tanh(fmaf(agg, W1[j], b1[j]));

    float l0 = b2[0], l1 = b2[1];
    #pragma unroll
    for (int j = 0; j < 4; j++) {
        l0 = fmaf(W2[j],     h[j], l0);
        l1 = fmaf(W2[4 + j], h[j], l1);
    }

    const float LOG2E = 1.4426950408889634f;
    float mx = fmaxf(l0, l1);
    float e0 = ex2_approx((l0 - mx) * LOG2E);
    float e1 = ex2_approx((l1 - mx) * LOG2E);
    float inv = rcp_approx(e0 + e1);
    out[2 * n + 0] = e0 * inv;
    out[2 * n + 1] = e1 * inv;
}

// -------------------------------------------------------------------------
extern "C" void kernel_launch(void* const* d_in, const int* in_sizes, int n_in,
                              void* d_out, int out_size)
{
    const float* x           = (const float*)d_in[0];
    const float* layer_W     = (const float*)d_in[1];
    const float* layer_b     = (const float*)d_in[2];
    const float* layer_scale = (const float*)d_in[3];
    const float* layer_shift = (const float*)d_in[4];
    const float* refset      = (const float*)d_in[5];
    const float* W1          = (const float*)d_in[6];
    const float* b1          = (const float*)d_in[7];
    const float* W2          = (const float*)d_in[8];
    const float* b2          = (const float*)d_in[9];
    float* out = (float*)d_out;

    prep_kernel<<<SBLK + N_PTS / TPB, TPB>>>(x, layer_W, layer_b,
                                             layer_scale, layer_shift, refset);
    final_kernel<<<N_PTS / TPB, TPB>>>(W1, b1, W2, b2, out);
}